// round 2
// baseline (speedup 1.0000x reference)
#include <cuda_runtime.h>

#define NN 50000
#define HH 128
#define GG 512
#define CC 10
#define GEMM_TM 64
#define GEMM_SMEM ((HH*HH + GEMM_TM*HH) * 4)   // Ws + Xs = 96 KB

__device__ __align__(16) float g_dis[NN];
__device__ __align__(16) float g_A[NN * HH];
__device__ __align__(16) float g_B[NN * HH];
__device__ __align__(16) float g_pool[GG * HH];
__device__ float g_cnt[GG];
__device__ int g_ei64;
__device__ int g_b64;

// ---------------------------------------------------------------------------
// Detect whether edge_index / batch buffers are int64 or int32.
// int64 values are < 2^31 and nonnegative, so every odd 32-bit word is 0.
// For int32 data (node ids / sorted graph ids) the OR of 1024 odd words is
// nonzero with certainty for this problem. Deterministic per input.
// ---------------------------------------------------------------------------
__global__ void detect_kernel(const unsigned* __restrict__ ei,
                              const unsigned* __restrict__ bat) {
    unsigned oe = 0, ob = 0;
    int lane = threadIdx.x;
    for (int i = lane; i < 1024; i += 32) {
        oe |= ei[2 * i + 1];
        ob |= bat[2 * i + 1];
    }
#pragma unroll
    for (int off = 16; off; off >>= 1) {
        oe |= __shfl_xor_sync(0xffffffffu, oe, off);
        ob |= __shfl_xor_sync(0xffffffffu, ob, off);
    }
    if (lane == 0) {
        g_ei64 = (oe == 0u);
        g_b64  = (ob == 0u);
    }
}

__global__ void init_kernel() {
    int i = blockIdx.x * blockDim.x + threadIdx.x;
    if (i < NN) g_dis[i] = 1.0f;               // +1 self-loop degree
    if (i < GG * HH) g_pool[i] = 0.0f;
    if (i < GG) g_cnt[i] = 0.0f;
}

__global__ void deg_kernel(const void* __restrict__ ei, int E) {
    int e = blockIdx.x * blockDim.x + threadIdx.x;
    if (e >= E) return;
    int dst = g_ei64 ? (int)((const long long*)ei)[E + e]
                     : ((const int*)ei)[E + e];
    atomicAdd(&g_dis[dst], 1.0f);
}

__global__ void rsqrt_kernel() {
    int i = blockIdx.x * blockDim.x + threadIdx.x;
    if (i < NN) g_dis[i] = rsqrtf(g_dis[i]);
}

// ---------------------------------------------------------------------------
// SGEMM: out[r][c] = sum_k X[r][k] * W[k][c], K = H = 128.
// Block: 256 threads, 64-row tile, thread micro-tile 8x4.
// Epilogue fuses the GCN self-loop: outAgg = h * dis[r]^2.
// In-place safe (X tile fully staged to SMEM before any writes).
// ---------------------------------------------------------------------------
__global__ void gemm_kernel(const float* __restrict__ X,
                            const float* __restrict__ W,
                            float* __restrict__ outH,
                            float* __restrict__ outAgg) {
    extern __shared__ float sm[];
    float* Ws = sm;                 // 128*128
    float* Xs = sm + HH * HH;       // 64*128
    int tid = threadIdx.x;
    int r0 = blockIdx.x * GEMM_TM;

#pragma unroll
    for (int j = 0; j < 16; j++) {                 // 4096 float4 of W
        int f = tid + j * 256;
        ((float4*)Ws)[f] = ((const float4*)W)[f];
    }
#pragma unroll
    for (int j = 0; j < 8; j++) {                  // 2048 float4 of X tile
        int f = tid + j * 256;
        int row = f >> 5;
        int gr = r0 + row;
        float4 v = make_float4(0.f, 0.f, 0.f, 0.f);
        if (gr < NN) v = ((const float4*)X)[gr * 32 + (f & 31)];
        ((float4*)Xs)[f] = v;
    }
    __syncthreads();

    int tx = tid & 31, ty = tid >> 5;
    float acc[8][4];
#pragma unroll
    for (int i = 0; i < 8; i++)
#pragma unroll
        for (int j = 0; j < 4; j++) acc[i][j] = 0.f;

#pragma unroll 4
    for (int k = 0; k < HH; k++) {
        float4 w = ((float4*)Ws)[k * 32 + tx];
#pragma unroll
        for (int i = 0; i < 8; i++) {
            float xv = Xs[(ty * 8 + i) * HH + k];   // warp broadcast
            acc[i][0] += xv * w.x;
            acc[i][1] += xv * w.y;
            acc[i][2] += xv * w.z;
            acc[i][3] += xv * w.w;
        }
    }

#pragma unroll
    for (int i = 0; i < 8; i++) {
        int r = r0 + ty * 8 + i;
        if (r < NN) {
            float d = g_dis[r];
            float d2 = d * d;
            float4 hv = make_float4(acc[i][0], acc[i][1], acc[i][2], acc[i][3]);
            ((float4*)outH)[r * 32 + tx] = hv;
            float4 av = make_float4(hv.x * d2, hv.y * d2, hv.z * d2, hv.w * d2);
            ((float4*)outAgg)[r * 32 + tx] = av;
        }
    }
}

// ---------------------------------------------------------------------------
// Edge message passing: one warp per edge.
// agg[dst] += h[src] * dis[src]*dis[dst]  via red.global.add.v4.f32
// ---------------------------------------------------------------------------
__global__ void edge_kernel(const void* __restrict__ ei,
                            const float* __restrict__ h,
                            float* __restrict__ agg, int E) {
    int w = (blockIdx.x * blockDim.x + threadIdx.x) >> 5;
    int lane = threadIdx.x & 31;
    if (w >= E) return;
    long long src, dst;
    if (g_ei64) {
        src = ((const long long*)ei)[w];
        dst = ((const long long*)ei)[E + w];
    } else {
        src = ((const int*)ei)[w];
        dst = ((const int*)ei)[E + w];
    }
    float nrm = g_dis[src] * g_dis[dst];
    float4 v = ((const float4*)h)[src * 32 + lane];
    v.x *= nrm; v.y *= nrm; v.z *= nrm; v.w *= nrm;
    float* p = agg + dst * HH + lane * 4;
    asm volatile("red.global.add.v4.f32 [%0], {%1,%2,%3,%4};"
                 :: "l"(p), "f"(v.x), "f"(v.y), "f"(v.z), "f"(v.w)
                 : "memory");
}

__global__ void relu_bias_kernel(const float* __restrict__ agg,
                                 const float* __restrict__ b,
                                 float* __restrict__ out) {
    int i = blockIdx.x * blockDim.x + threadIdx.x;   // float4 index
    if (i >= NN * 32) return;
    float4 v = ((const float4*)agg)[i];
    int c = (i & 31) * 4;
    v.x = fmaxf(v.x + __ldg(b + c + 0), 0.f);
    v.y = fmaxf(v.y + __ldg(b + c + 1), 0.f);
    v.z = fmaxf(v.z + __ldg(b + c + 2), 0.f);
    v.w = fmaxf(v.w + __ldg(b + c + 3), 0.f);
    ((float4*)out)[i] = v;
}

__global__ void pool_kernel(const void* __restrict__ bat,
                            const float* __restrict__ h) {
    int w = (blockIdx.x * blockDim.x + threadIdx.x) >> 5;
    int lane = threadIdx.x & 31;
    if (w >= NN) return;
    int b = g_b64 ? (int)((const long long*)bat)[w] : ((const int*)bat)[w];
    float4 v = ((const float4*)h)[w * 32 + lane];
    float* p = g_pool + b * HH + lane * 4;
    asm volatile("red.global.add.v4.f32 [%0], {%1,%2,%3,%4};"
                 :: "l"(p), "f"(v.x), "f"(v.y), "f"(v.z), "f"(v.w)
                 : "memory");
    if (lane == 0) atomicAdd(&g_cnt[b], 1.0f);
}

__global__ void final_kernel(const float* __restrict__ Wl,
                             const float* __restrict__ bl,
                             float* __restrict__ out) {
    int g = blockIdx.x;
    int lane = threadIdx.x;
    float c = fmaxf(g_cnt[g], 1.0f);
    float inv = 1.0f / c;
    float4 p = ((const float4*)g_pool)[g * 32 + lane];
    p.x *= inv; p.y *= inv; p.z *= inv; p.w *= inv;
    int r = lane * 4;
#pragma unroll
    for (int j = 0; j < CC; j++) {
        float s = p.x * __ldg(Wl + (r + 0) * CC + j)
                + p.y * __ldg(Wl + (r + 1) * CC + j)
                + p.z * __ldg(Wl + (r + 2) * CC + j)
                + p.w * __ldg(Wl + (r + 3) * CC + j);
#pragma unroll
        for (int off = 16; off; off >>= 1)
            s += __shfl_xor_sync(0xffffffffu, s, off);
        if (lane == 0) out[g * CC + j] = s + __ldg(bl + j);
    }
}

extern "C" void kernel_launch(void* const* d_in, const int* in_sizes, int n_in,
                              void* d_out, int out_size) {
    const float* x  = (const float*)d_in[0];
    const void*  ei = d_in[1];
    const void*  bat = d_in[2];
    const float* W1 = (const float*)d_in[3];
    const float* b1 = (const float*)d_in[4];
    const float* W2 = (const float*)d_in[5];
    const float* b2 = (const float*)d_in[6];
    const float* Wl = (const float*)d_in[7];
    const float* bl = (const float*)d_in[8];
    float* out = (float*)d_out;
    int E = in_sizes[1] / 2;

    cudaFuncSetAttribute(gemm_kernel,
                         cudaFuncAttributeMaxDynamicSharedMemorySize, GEMM_SMEM);

    float *A, *B;
    cudaGetSymbolAddress((void**)&A, g_A);
    cudaGetSymbolAddress((void**)&B, g_B);

    detect_kernel<<<1, 32>>>((const unsigned*)ei, (const unsigned*)bat);
    init_kernel<<<(GG * HH + 255) / 256, 256>>>();
    deg_kernel<<<(E + 255) / 256, 256>>>(ei, E);
    rsqrt_kernel<<<(NN + 255) / 256, 256>>>();

    int gemm_blocks = (NN + GEMM_TM - 1) / GEMM_TM;
    int edge_blocks = (E * 32 + 255) / 256;
    int elem_blocks = (NN * 32 + 255) / 256;

    // Layer 1
    gemm_kernel<<<gemm_blocks, 256, GEMM_SMEM>>>(x, W1, A, B);
    edge_kernel<<<edge_blocks, 256>>>(ei, A, B, E);
    relu_bias_kernel<<<elem_blocks, 256>>>(B, b1, A);

    // Layer 2 (GEMM in place: A -> A)
    gemm_kernel<<<gemm_blocks, 256, GEMM_SMEM>>>(A, W2, A, B);
    edge_kernel<<<edge_blocks, 256>>>(ei, A, B, E);
    relu_bias_kernel<<<elem_blocks, 256>>>(B, b2, A);

    // Pool + head
    pool_kernel<<<elem_blocks, 256>>>(bat, A);
    final_kernel<<<GG, 32>>>(Wl, bl, out);
}

// round 4
// speedup vs baseline: 1.2132x; 1.2132x over previous
#include <cuda_runtime.h>
#include <cstdint>

#define NN 50000
#define HH 128
#define GG 512
#define CC 10
#define EMAX 800000
#define TS 132   // padded SMEM row stride (floats)

// ---------------- scratch (no allocs allowed) ----------------
__device__ __align__(16) float g_dis[NN];
__device__ __align__(16) float g_A[NN * HH];
__device__ __align__(16) float g_B[NN * HH];
__device__ __align__(16) float g_pool[GG * HH];
__device__ float g_cnt[GG];
__device__ int   g_deg[NN];
__device__ int   g_off[NN + 1];
__device__ int   g_cur[NN];
__device__ int   g_csr[EMAX];
__device__ int g_ei64;
__device__ int g_b64;

// ---------------- dtype detect (int64 vs int32 buffers) ----------------
__global__ void detect_kernel(const unsigned* __restrict__ ei,
                              const unsigned* __restrict__ bat) {
    unsigned oe = 0, ob = 0;
    int lane = threadIdx.x;
    for (int i = lane; i < 1024; i += 32) {
        oe |= ei[2 * i + 1];
        ob |= bat[2 * i + 1];
    }
#pragma unroll
    for (int off = 16; off; off >>= 1) {
        oe |= __shfl_xor_sync(0xffffffffu, oe, off);
        ob |= __shfl_xor_sync(0xffffffffu, ob, off);
    }
    if (lane == 0) { g_ei64 = (oe == 0u); g_b64 = (ob == 0u); }
}

__global__ void init_kernel() {
    int i = blockIdx.x * blockDim.x + threadIdx.x;
    if (i < NN) g_deg[i] = 0;
    if (i < GG * HH) g_pool[i] = 0.0f;
    if (i < GG) g_cnt[i] = 0.0f;
}

__global__ void deg_kernel(const void* __restrict__ ei, int E) {
    int e = blockIdx.x * blockDim.x + threadIdx.x;
    if (e >= E) return;
    int dst = g_ei64 ? (int)((const long long*)ei)[E + e] : ((const int*)ei)[E + e];
    atomicAdd(&g_deg[dst], 1);
}

// single block: exclusive scan -> offsets, cursors, dis = rsqrt(deg+1)
__global__ void scan_kernel() {
    __shared__ int ssum[1024];
    int t = threadIdx.x;
    const int NPT = (NN + 1023) / 1024;
    int beg = t * NPT, end = min(beg + NPT, NN);
    int s = 0;
    for (int i = beg; i < end; i++) s += g_deg[i];
    ssum[t] = s;
    __syncthreads();
    for (int off = 1; off < 1024; off <<= 1) {
        int v = (t >= off) ? ssum[t - off] : 0;
        __syncthreads();
        ssum[t] += v;
        __syncthreads();
    }
    int run = t ? ssum[t - 1] : 0;
    for (int i = beg; i < end; i++) {
        g_off[i] = run;
        g_cur[i] = run;
        run += g_deg[i];
        g_dis[i] = rsqrtf((float)g_deg[i] + 1.0f);
    }
    if (t == 1023) g_off[NN] = ssum[1023];
}

__global__ void fill_kernel(const void* __restrict__ ei, int E) {
    int e = blockIdx.x * blockDim.x + threadIdx.x;
    if (e >= E) return;
    int src, dst;
    if (g_ei64) {
        src = (int)((const long long*)ei)[e];
        dst = (int)((const long long*)ei)[E + e];
    } else {
        src = ((const int*)ei)[e];
        dst = ((const int*)ei)[E + e];
    }
    int slot = atomicAdd(&g_cur[dst], 1);
    g_csr[slot] = src;
}

// ---------------------------------------------------------------------------
// tf32 HMMA GEMM: out[128-row tile][128] = X @ W, K=128.
// 256 threads = 8 warps in 4x2 grid; warp tile 32x64 = 2x8 m16n8k8 subtiles.
// A row-major from Xs, B col-major fragments index W[k][n] directly.
// Inputs rounded to tf32 (cvt.rna) at SMEM stage-in.
// ---------------------------------------------------------------------------
__device__ __forceinline__ float to_tf32(float f) {
    uint32_t o;
    asm("cvt.rna.tf32.f32 %0, %1;" : "=r"(o) : "f"(f));
    return __uint_as_float(o);
}

__global__ void __launch_bounds__(256, 1)
gemm_mma(const float* __restrict__ X, const float* __restrict__ W,
         float* __restrict__ out) {
    extern __shared__ float sm[];
    float* Xs = sm;              // 128 x TS
    float* Ws = sm + 128 * TS;   // 128 x TS
    int tid = threadIdx.x;
    int r0 = blockIdx.x * 128;

#pragma unroll
    for (int j = 0; j < 16; j++) {
        int f = tid + j * 256;          // 0..4095
        int row = f >> 5, c4 = f & 31;
        int gr = r0 + row;
        float4 v = make_float4(0.f, 0.f, 0.f, 0.f);
        if (gr < NN) v = ((const float4*)X)[gr * 32 + c4];
        v.x = to_tf32(v.x); v.y = to_tf32(v.y);
        v.z = to_tf32(v.z); v.w = to_tf32(v.w);
        *(float4*)(Xs + row * TS + c4 * 4) = v;
        float4 w = ((const float4*)W)[row * 32 + c4];
        w.x = to_tf32(w.x); w.y = to_tf32(w.y);
        w.z = to_tf32(w.z); w.w = to_tf32(w.w);
        *(float4*)(Ws + row * TS + c4 * 4) = w;
    }
    __syncthreads();

    int lane = tid & 31, wid = tid >> 5;
    int mw = (wid >> 1) * 32;       // warp row offset
    int nw = (wid & 1) * 64;        // warp col offset
    int gq = lane >> 2;             // group (0..7)
    int tq = lane & 3;              // thread-in-group (0..3)

    float acc[2][8][4];
#pragma unroll
    for (int m = 0; m < 2; m++)
#pragma unroll
        for (int n = 0; n < 8; n++)
#pragma unroll
            for (int q = 0; q < 4; q++) acc[m][n][q] = 0.f;

#pragma unroll
    for (int kt = 0; kt < 16; kt++) {
        int k0 = kt * 8;
        uint32_t b0[8], b1[8];
        const float* wrow0 = Ws + (k0 + tq) * TS + nw + gq;
        const float* wrow1 = wrow0 + 4 * TS;
#pragma unroll
        for (int n = 0; n < 8; n++) {
            b0[n] = __float_as_uint(wrow0[n * 8]);
            b1[n] = __float_as_uint(wrow1[n * 8]);
        }
        uint32_t a[2][4];
#pragma unroll
        for (int m = 0; m < 2; m++) {
            const float* xr = Xs + (mw + m * 16 + gq) * TS + k0 + tq;
            a[m][0] = __float_as_uint(xr[0]);
            a[m][1] = __float_as_uint(xr[8 * TS]);
            a[m][2] = __float_as_uint(xr[4]);
            a[m][3] = __float_as_uint(xr[8 * TS + 4]);
        }
#pragma unroll
        for (int m = 0; m < 2; m++)
#pragma unroll
            for (int n = 0; n < 8; n++)
                asm volatile(
                    "mma.sync.aligned.m16n8k8.row.col.f32.tf32.tf32.f32 "
                    "{%0,%1,%2,%3}, {%4,%5,%6,%7}, {%8,%9}, {%0,%1,%2,%3};"
                    : "+f"(acc[m][n][0]), "+f"(acc[m][n][1]),
                      "+f"(acc[m][n][2]), "+f"(acc[m][n][3])
                    : "r"(a[m][0]), "r"(a[m][1]), "r"(a[m][2]), "r"(a[m][3]),
                      "r"(b0[n]), "r"(b1[n]));
    }

#pragma unroll
    for (int m = 0; m < 2; m++) {
        int r = r0 + mw + m * 16 + gq;
#pragma unroll
        for (int n = 0; n < 8; n++) {
            int c = nw + n * 8 + 2 * tq;
            if (r < NN)
                *(float2*)(out + r * HH + c) = make_float2(acc[m][n][0], acc[m][n][1]);
            if (r + 8 < NN)
                *(float2*)(out + (r + 8) * HH + c) = make_float2(acc[m][n][2], acc[m][n][3]);
        }
    }
}

// ---------------- CSR aggregation: warp per dst, fused self-loop+bias+relu ----
__global__ void agg_kernel(const float* __restrict__ h,
                           const float* __restrict__ bias,
                           float* __restrict__ out) {
    int w = (blockIdx.x * blockDim.x + threadIdx.x) >> 5;
    int lane = threadIdx.x & 31;
    if (w >= NN) return;
    float dd = g_dis[w];
    float sc = dd * dd;
    float4 acc = ((const float4*)h)[w * 32 + lane];
    acc.x *= sc; acc.y *= sc; acc.z *= sc; acc.w *= sc;
    int beg = g_off[w], end = g_off[w + 1];
    int snext = (beg < end) ? g_csr[beg] : 0;
    for (int e = beg; e < end; e++) {
        int s = snext;
        if (e + 1 < end) snext = g_csr[e + 1];
        float nr = g_dis[s] * dd;
        float4 v = ((const float4*)h)[s * 32 + lane];
        acc.x = fmaf(v.x, nr, acc.x);
        acc.y = fmaf(v.y, nr, acc.y);
        acc.z = fmaf(v.z, nr, acc.z);
        acc.w = fmaf(v.w, nr, acc.w);
    }
    int c = lane * 4;
    acc.x = fmaxf(acc.x + __ldg(bias + c + 0), 0.f);
    acc.y = fmaxf(acc.y + __ldg(bias + c + 1), 0.f);
    acc.z = fmaxf(acc.z + __ldg(bias + c + 2), 0.f);
    acc.w = fmaxf(acc.w + __ldg(bias + c + 3), 0.f);
    ((float4*)out)[w * 32 + lane] = acc;
}

__global__ void pool_kernel(const void* __restrict__ bat,
                            const float* __restrict__ h) {
    int w = (blockIdx.x * blockDim.x + threadIdx.x) >> 5;
    int lane = threadIdx.x & 31;
    if (w >= NN) return;
    int b = g_b64 ? (int)((const long long*)bat)[w] : ((const int*)bat)[w];
    float4 v = ((const float4*)h)[w * 32 + lane];
    float* p = g_pool + b * HH + lane * 4;
    asm volatile("red.global.add.v4.f32 [%0], {%1,%2,%3,%4};"
                 :: "l"(p), "f"(v.x), "f"(v.y), "f"(v.z), "f"(v.w) : "memory");
    if (lane == 0) atomicAdd(&g_cnt[b], 1.0f);
}

__global__ void final_kernel(const float* __restrict__ Wl,
                             const float* __restrict__ bl,
                             float* __restrict__ out) {
    int g = blockIdx.x;
    int lane = threadIdx.x;
    float c = fmaxf(g_cnt[g], 1.0f);
    float inv = 1.0f / c;
    float4 p = ((const float4*)g_pool)[g * 32 + lane];
    p.x *= inv; p.y *= inv; p.z *= inv; p.w *= inv;
    int r = lane * 4;
#pragma unroll
    for (int j = 0; j < CC; j++) {
        float s = p.x * __ldg(Wl + (r + 0) * CC + j)
                + p.y * __ldg(Wl + (r + 1) * CC + j)
                + p.z * __ldg(Wl + (r + 2) * CC + j)
                + p.w * __ldg(Wl + (r + 3) * CC + j);
#pragma unroll
        for (int off = 16; off; off >>= 1)
            s += __shfl_xor_sync(0xffffffffu, s, off);
        if (lane == 0) out[g * CC + j] = s + __ldg(bl + j);
    }
}

extern "C" void kernel_launch(void* const* d_in, const int* in_sizes, int n_in,
                              void* d_out, int out_size) {
    const float* x  = (const float*)d_in[0];
    const void*  ei = d_in[1];
    const void*  bat = d_in[2];
    const float* W1 = (const float*)d_in[3];
    const float* b1 = (const float*)d_in[4];
    const float* W2 = (const float*)d_in[5];
    const float* b2 = (const float*)d_in[6];
    const float* Wl = (const float*)d_in[7];
    const float* bl = (const float*)d_in[8];
    float* out = (float*)d_out;
    int E = in_sizes[1] / 2;

    const int SMEM_GEMM = 2 * 128 * TS * 4;   // 135168 B
    static int smem_set = 0;
    if (!smem_set) {
        cudaFuncSetAttribute(gemm_mma, cudaFuncAttributeMaxDynamicSharedMemorySize,
                             SMEM_GEMM);
        smem_set = 1;
    }

    float *A, *B;
    cudaGetSymbolAddress((void**)&A, g_A);
    cudaGetSymbolAddress((void**)&B, g_B);

    int eb = (E + 255) / 256;
    int nb32 = (NN * 32 + 255) / 256;
    int gb = (NN + 127) / 128;

    detect_kernel<<<1, 32>>>((const unsigned*)ei, (const unsigned*)bat);
    init_kernel<<<256, 256>>>();
    deg_kernel<<<eb, 256>>>(ei, E);
    scan_kernel<<<1, 1024>>>();
    fill_kernel<<<eb, 256>>>(ei, E);

    gemm_mma<<<gb, 256, SMEM_GEMM>>>(x, W1, A);
    agg_kernel<<<nb32, 256>>>(A, b1, B);
    gemm_mma<<<gb, 256, SMEM_GEMM>>>(B, W2, A);
    agg_kernel<<<nb32, 256>>>(A, b2, B);

    pool_kernel<<<nb32, 256>>>(bat, B);
    final_kernel<<<GG, 32>>>(Wl, bl, out);
}

// round 5
// speedup vs baseline: 1.9395x; 1.5987x over previous
#include <cuda_runtime.h>
#include <cstdint>

#define NN 50000
#define HH 128
#define GG 512
#define CC 10
#define EMAX 800000
#define TS 132   // padded SMEM row stride (floats)
#define SCAN_B 196   // ceil(NN/256)

// ---------------- scratch (no allocs allowed) ----------------
__device__ __align__(16) float g_dis[NN];
__device__ __align__(16) float g_A[NN * HH];
__device__ __align__(16) float g_B[NN * HH];
__device__ __align__(16) float g_pool[GG * HH];
__device__ float g_cnt[GG];
__device__ int   g_deg[NN];
__device__ int   g_off[NN + 1];
__device__ int   g_cur[NN];
__device__ int   g_csr[EMAX];
__device__ int   g_bsum[SCAN_B];
__device__ int g_ei64;
__device__ int g_b64;

// ---------------- dtype detect (int64 vs int32 buffers) ----------------
__global__ void detect_kernel(const unsigned* __restrict__ ei,
                              const unsigned* __restrict__ bat) {
    unsigned oe = 0, ob = 0;
    int lane = threadIdx.x;
    for (int i = lane; i < 1024; i += 32) {
        oe |= ei[2 * i + 1];
        ob |= bat[2 * i + 1];
    }
#pragma unroll
    for (int off = 16; off; off >>= 1) {
        oe |= __shfl_xor_sync(0xffffffffu, oe, off);
        ob |= __shfl_xor_sync(0xffffffffu, ob, off);
    }
    if (lane == 0) { g_ei64 = (oe == 0u); g_b64 = (ob == 0u); }
}

__global__ void init_kernel() {
    int i = blockIdx.x * blockDim.x + threadIdx.x;
    if (i < NN) g_deg[i] = 0;
    if (i < GG * HH) g_pool[i] = 0.0f;
    if (i < GG) g_cnt[i] = 0.0f;
}

__global__ void deg_kernel(const void* __restrict__ ei, int E) {
    int e = blockIdx.x * blockDim.x + threadIdx.x;
    if (e >= E) return;
    int dst = g_ei64 ? (int)((const long long*)ei)[E + e] : ((const int*)ei)[E + e];
    atomicAdd(&g_deg[dst], 1);
}

// ---------------- 3-phase chip-wide exclusive scan of g_deg ----------------
__global__ void blocksum_kernel() {                 // grid SCAN_B, block 256
    int i = blockIdx.x * 256 + threadIdx.x;
    int d = (i < NN) ? g_deg[i] : 0;
    __shared__ int ws[8];
    int lane = threadIdx.x & 31, wid = threadIdx.x >> 5;
    int s = d;
#pragma unroll
    for (int off = 16; off; off >>= 1) s += __shfl_xor_sync(0xffffffffu, s, off);
    if (lane == 0) ws[wid] = s;
    __syncthreads();
    if (threadIdx.x == 0) {
        int t = 0;
#pragma unroll
        for (int w = 0; w < 8; w++) t += ws[w];
        g_bsum[blockIdx.x] = t;
    }
}

__global__ void scanpart_kernel() {                 // 1 block, 256 threads
    __shared__ int sh[256];
    int t = threadIdx.x;
    int v = (t < SCAN_B) ? g_bsum[t] : 0;
    sh[t] = v;
    __syncthreads();
    for (int off = 1; off < 256; off <<= 1) {
        int u = (t >= off) ? sh[t - off] : 0;
        __syncthreads();
        sh[t] += u;
        __syncthreads();
    }
    if (t < SCAN_B) g_bsum[t] = sh[t] - v;          // exclusive
}

__global__ void offsets_kernel() {                  // grid SCAN_B, block 256
    __shared__ int ws[8];
    int i = blockIdx.x * 256 + threadIdx.x;
    int lane = threadIdx.x & 31, wid = threadIdx.x >> 5;
    int d = (i < NN) ? g_deg[i] : 0;
    int incl = d;
#pragma unroll
    for (int off = 1; off < 32; off <<= 1) {
        int u = __shfl_up_sync(0xffffffffu, incl, off);
        if (lane >= off) incl += u;
    }
    if (lane == 31) ws[wid] = incl;
    __syncthreads();
    int wpre = 0;
#pragma unroll
    for (int w = 0; w < 8; w++) wpre += (w < wid) ? ws[w] : 0;
    int base = g_bsum[blockIdx.x] + wpre;
    int off0 = base + incl - d;
    if (i < NN) {
        g_off[i] = off0;
        g_cur[i] = off0;
        g_dis[i] = rsqrtf((float)d + 1.0f);
        if (i == NN - 1) g_off[NN] = off0 + d;
    }
}

__global__ void fill_kernel(const void* __restrict__ ei, int E) {
    int e = blockIdx.x * blockDim.x + threadIdx.x;
    if (e >= E) return;
    int src, dst;
    if (g_ei64) {
        src = (int)((const long long*)ei)[e];
        dst = (int)((const long long*)ei)[E + e];
    } else {
        src = ((const int*)ei)[e];
        dst = ((const int*)ei)[E + e];
    }
    int slot = atomicAdd(&g_cur[dst], 1);
    g_csr[slot] = src;
}

// ---------------------------------------------------------------------------
// tf32 HMMA GEMM: out[128-row tile][128] = X @ W, K=128.
// ---------------------------------------------------------------------------
__device__ __forceinline__ float to_tf32(float f) {
    uint32_t o;
    asm("cvt.rna.tf32.f32 %0, %1;" : "=r"(o) : "f"(f));
    return __uint_as_float(o);
}

__global__ void __launch_bounds__(256, 1)
gemm_mma(const float* __restrict__ X, const float* __restrict__ W,
         float* __restrict__ out) {
    extern __shared__ float sm[];
    float* Xs = sm;              // 128 x TS
    float* Ws = sm + 128 * TS;   // 128 x TS
    int tid = threadIdx.x;
    int r0 = blockIdx.x * 128;

#pragma unroll
    for (int j = 0; j < 16; j++) {
        int f = tid + j * 256;          // 0..4095
        int row = f >> 5, c4 = f & 31;
        int gr = r0 + row;
        float4 v = make_float4(0.f, 0.f, 0.f, 0.f);
        if (gr < NN) v = ((const float4*)X)[gr * 32 + c4];
        v.x = to_tf32(v.x); v.y = to_tf32(v.y);
        v.z = to_tf32(v.z); v.w = to_tf32(v.w);
        *(float4*)(Xs + row * TS + c4 * 4) = v;
        float4 w = ((const float4*)W)[row * 32 + c4];
        w.x = to_tf32(w.x); w.y = to_tf32(w.y);
        w.z = to_tf32(w.z); w.w = to_tf32(w.w);
        *(float4*)(Ws + row * TS + c4 * 4) = w;
    }
    __syncthreads();

    int lane = tid & 31, wid = tid >> 5;
    int mw = (wid >> 1) * 32;       // warp row offset
    int nw = (wid & 1) * 64;        // warp col offset
    int gq = lane >> 2;             // group (0..7)
    int tq = lane & 3;              // thread-in-group (0..3)

    float acc[2][8][4];
#pragma unroll
    for (int m = 0; m < 2; m++)
#pragma unroll
        for (int n = 0; n < 8; n++)
#pragma unroll
            for (int q = 0; q < 4; q++) acc[m][n][q] = 0.f;

#pragma unroll
    for (int kt = 0; kt < 16; kt++) {
        int k0 = kt * 8;
        uint32_t b0[8], b1[8];
        const float* wrow0 = Ws + (k0 + tq) * TS + nw + gq;
        const float* wrow1 = wrow0 + 4 * TS;
#pragma unroll
        for (int n = 0; n < 8; n++) {
            b0[n] = __float_as_uint(wrow0[n * 8]);
            b1[n] = __float_as_uint(wrow1[n * 8]);
        }
        uint32_t a[2][4];
#pragma unroll
        for (int m = 0; m < 2; m++) {
            const float* xr = Xs + (mw + m * 16 + gq) * TS + k0 + tq;
            a[m][0] = __float_as_uint(xr[0]);
            a[m][1] = __float_as_uint(xr[8 * TS]);
            a[m][2] = __float_as_uint(xr[4]);
            a[m][3] = __float_as_uint(xr[8 * TS + 4]);
        }
#pragma unroll
        for (int m = 0; m < 2; m++)
#pragma unroll
            for (int n = 0; n < 8; n++)
                asm volatile(
                    "mma.sync.aligned.m16n8k8.row.col.f32.tf32.tf32.f32 "
                    "{%0,%1,%2,%3}, {%4,%5,%6,%7}, {%8,%9}, {%0,%1,%2,%3};"
                    : "+f"(acc[m][n][0]), "+f"(acc[m][n][1]),
                      "+f"(acc[m][n][2]), "+f"(acc[m][n][3])
                    : "r"(a[m][0]), "r"(a[m][1]), "r"(a[m][2]), "r"(a[m][3]),
                      "r"(b0[n]), "r"(b1[n]));
    }

#pragma unroll
    for (int m = 0; m < 2; m++) {
        int r = r0 + mw + m * 16 + gq;
#pragma unroll
        for (int n = 0; n < 8; n++) {
            int c = nw + n * 8 + 2 * tq;
            if (r < NN)
                *(float2*)(out + r * HH + c) = make_float2(acc[m][n][0], acc[m][n][1]);
            if (r + 8 < NN)
                *(float2*)(out + (r + 8) * HH + c) = make_float2(acc[m][n][2], acc[m][n][3]);
        }
    }
}

// ---------------- CSR aggregation: warp per dst, fused self-loop+bias+relu ----
__global__ void agg_kernel(const float* __restrict__ h,
                           const float* __restrict__ bias,
                           float* __restrict__ out) {
    int w = (blockIdx.x * blockDim.x + threadIdx.x) >> 5;
    int lane = threadIdx.x & 31;
    if (w >= NN) return;
    float dd = g_dis[w];
    float sc = dd * dd;
    float4 acc = ((const float4*)h)[w * 32 + lane];
    acc.x *= sc; acc.y *= sc; acc.z *= sc; acc.w *= sc;
    int beg = g_off[w], end = g_off[w + 1];
    int snext = (beg < end) ? g_csr[beg] : 0;
    for (int e = beg; e < end; e++) {
        int s = snext;
        if (e + 1 < end) snext = g_csr[e + 1];
        float nr = g_dis[s] * dd;
        float4 v = ((const float4*)h)[s * 32 + lane];
        acc.x = fmaf(v.x, nr, acc.x);
        acc.y = fmaf(v.y, nr, acc.y);
        acc.z = fmaf(v.z, nr, acc.z);
        acc.w = fmaf(v.w, nr, acc.w);
    }
    int c = lane * 4;
    acc.x = fmaxf(acc.x + __ldg(bias + c + 0), 0.f);
    acc.y = fmaxf(acc.y + __ldg(bias + c + 1), 0.f);
    acc.z = fmaxf(acc.z + __ldg(bias + c + 2), 0.f);
    acc.w = fmaxf(acc.w + __ldg(bias + c + 3), 0.f);
    ((float4*)out)[w * 32 + lane] = acc;
}

__global__ void pool_kernel(const void* __restrict__ bat,
                            const float* __restrict__ h) {
    int w = (blockIdx.x * blockDim.x + threadIdx.x) >> 5;
    int lane = threadIdx.x & 31;
    if (w >= NN) return;
    int b = g_b64 ? (int)((const long long*)bat)[w] : ((const int*)bat)[w];
    float4 v = ((const float4*)h)[w * 32 + lane];
    float* p = g_pool + b * HH + lane * 4;
    asm volatile("red.global.add.v4.f32 [%0], {%1,%2,%3,%4};"
                 :: "l"(p), "f"(v.x), "f"(v.y), "f"(v.z), "f"(v.w) : "memory");
    if (lane == 0) atomicAdd(&g_cnt[b], 1.0f);
}

__global__ void final_kernel(const float* __restrict__ Wl,
                             const float* __restrict__ bl,
                             float* __restrict__ out) {
    int g = blockIdx.x;
    int lane = threadIdx.x;
    float c = fmaxf(g_cnt[g], 1.0f);
    float inv = 1.0f / c;
    float4 p = ((const float4*)g_pool)[g * 32 + lane];
    p.x *= inv; p.y *= inv; p.z *= inv; p.w *= inv;
    int r = lane * 4;
#pragma unroll
    for (int j = 0; j < CC; j++) {
        float s = p.x * __ldg(Wl + (r + 0) * CC + j)
                + p.y * __ldg(Wl + (r + 1) * CC + j)
                + p.z * __ldg(Wl + (r + 2) * CC + j)
                + p.w * __ldg(Wl + (r + 3) * CC + j);
#pragma unroll
        for (int off = 16; off; off >>= 1)
            s += __shfl_xor_sync(0xffffffffu, s, off);
        if (lane == 0) out[g * CC + j] = s + __ldg(bl + j);
    }
}

extern "C" void kernel_launch(void* const* d_in, const int* in_sizes, int n_in,
                              void* d_out, int out_size) {
    const float* x  = (const float*)d_in[0];
    const void*  ei = d_in[1];
    const void*  bat = d_in[2];
    const float* W1 = (const float*)d_in[3];
    const float* b1 = (const float*)d_in[4];
    const float* W2 = (const float*)d_in[5];
    const float* b2 = (const float*)d_in[6];
    const float* Wl = (const float*)d_in[7];
    const float* bl = (const float*)d_in[8];
    float* out = (float*)d_out;
    int E = in_sizes[1] / 2;

    const int SMEM_GEMM = 2 * 128 * TS * 4;   // 135168 B
    static int smem_set = 0;
    if (!smem_set) {
        cudaFuncSetAttribute(gemm_mma, cudaFuncAttributeMaxDynamicSharedMemorySize,
                             SMEM_GEMM);
        smem_set = 1;
    }

    float *A, *B;
    cudaGetSymbolAddress((void**)&A, g_A);
    cudaGetSymbolAddress((void**)&B, g_B);

    int eb = (E + 255) / 256;
    int nb32 = (NN * 32 + 255) / 256;
    int gb = (NN + 127) / 128;

    detect_kernel<<<1, 32>>>((const unsigned*)ei, (const unsigned*)bat);
    init_kernel<<<256, 256>>>();
    deg_kernel<<<eb, 256>>>(ei, E);
    blocksum_kernel<<<SCAN_B, 256>>>();
    scanpart_kernel<<<1, 256>>>();
    offsets_kernel<<<SCAN_B, 256>>>();
    fill_kernel<<<eb, 256>>>(ei, E);

    gemm_mma<<<gb, 256, SMEM_GEMM>>>(x, W1, A);
    agg_kernel<<<nb32, 256>>>(A, b1, B);
    gemm_mma<<<gb, 256, SMEM_GEMM>>>(B, W2, A);
    agg_kernel<<<nb32, 256>>>(A, b2, B);

    pool_kernel<<<nb32, 256>>>(bat, B);
    final_kernel<<<GG, 32>>>(Wl, bl, out);
}

// round 6
// speedup vs baseline: 2.3406x; 1.2068x over previous
#include <cuda_runtime.h>
#include <cstdint>

#define NN 50000
#define HH 128
#define GG 512
#define CC 10
#define EMAX 800000
#define TS 132        // padded SMEM row stride (floats)
#define SCAN_B 196    // ceil(NN/256)

// ---------------- scratch (no allocs allowed) ----------------
__device__ __align__(16) float g_dis[NN];
__device__ __align__(16) float g_A[NN * HH];
__device__ __align__(16) float g_B[NN * HH];
__device__ __align__(16) float g_pool[GG * HH];
__device__ float g_cnt[GG];
__device__ int   g_deg[NN];
__device__ int   g_off[NN + 1];
__device__ int   g_cur[NN];
__device__ int   g_csr[EMAX];
__device__ int   g_bsum[SCAN_B];
__device__ int g_ei64;
__device__ int g_b64;

// ---------------- init + dtype detect (merged) ----------------
__global__ void init_detect_kernel(const unsigned* __restrict__ ei,
                                   const unsigned* __restrict__ bat) {
    int i = blockIdx.x * blockDim.x + threadIdx.x;
    if (i < NN) g_deg[i] = 0;
    if (i < GG * HH) g_pool[i] = 0.0f;
    if (i < GG) g_cnt[i] = 0.0f;
    if (blockIdx.x == 0 && threadIdx.x < 32) {
        unsigned oe = 0, ob = 0;
        int lane = threadIdx.x;
        for (int j = lane; j < 1024; j += 32) {
            oe |= ei[2 * j + 1];
            ob |= bat[2 * j + 1];
        }
#pragma unroll
        for (int off = 16; off; off >>= 1) {
            oe |= __shfl_xor_sync(0xffffffffu, oe, off);
            ob |= __shfl_xor_sync(0xffffffffu, ob, off);
        }
        if (lane == 0) { g_ei64 = (oe == 0u); g_b64 = (ob == 0u); }
    }
}

__global__ void deg_kernel(const void* __restrict__ ei, int E) {
    int e = blockIdx.x * blockDim.x + threadIdx.x;
    if (e >= E) return;
    int dst = g_ei64 ? (int)((const long long*)ei)[E + e] : ((const int*)ei)[E + e];
    atomicAdd(&g_deg[dst], 1);
}

// ---------------- 3-phase chip-wide exclusive scan of g_deg ----------------
__global__ void blocksum_kernel() {
    int i = blockIdx.x * 256 + threadIdx.x;
    int d = (i < NN) ? g_deg[i] : 0;
    __shared__ int ws[8];
    int lane = threadIdx.x & 31, wid = threadIdx.x >> 5;
    int s = d;
#pragma unroll
    for (int off = 16; off; off >>= 1) s += __shfl_xor_sync(0xffffffffu, s, off);
    if (lane == 0) ws[wid] = s;
    __syncthreads();
    if (threadIdx.x == 0) {
        int t = 0;
#pragma unroll
        for (int w = 0; w < 8; w++) t += ws[w];
        g_bsum[blockIdx.x] = t;
    }
}

__global__ void scanpart_kernel() {
    __shared__ int sh[256];
    int t = threadIdx.x;
    int v = (t < SCAN_B) ? g_bsum[t] : 0;
    sh[t] = v;
    __syncthreads();
    for (int off = 1; off < 256; off <<= 1) {
        int u = (t >= off) ? sh[t - off] : 0;
        __syncthreads();
        sh[t] += u;
        __syncthreads();
    }
    if (t < SCAN_B) g_bsum[t] = sh[t] - v;          // exclusive
}

__global__ void offsets_kernel() {
    __shared__ int ws[8];
    int i = blockIdx.x * 256 + threadIdx.x;
    int lane = threadIdx.x & 31, wid = threadIdx.x >> 5;
    int d = (i < NN) ? g_deg[i] : 0;
    int incl = d;
#pragma unroll
    for (int off = 1; off < 32; off <<= 1) {
        int u = __shfl_up_sync(0xffffffffu, incl, off);
        if (lane >= off) incl += u;
    }
    if (lane == 31) ws[wid] = incl;
    __syncthreads();
    int wpre = 0;
#pragma unroll
    for (int w = 0; w < 8; w++) wpre += (w < wid) ? ws[w] : 0;
    int base = g_bsum[blockIdx.x] + wpre;
    int off0 = base + incl - d;
    if (i < NN) {
        g_off[i] = off0;
        g_cur[i] = off0;
        g_dis[i] = rsqrtf((float)d + 1.0f);
        if (i == NN - 1) g_off[NN] = off0 + d;
    }
}

__global__ void fill_kernel(const void* __restrict__ ei, int E) {
    int e = blockIdx.x * blockDim.x + threadIdx.x;
    if (e >= E) return;
    int src, dst;
    if (g_ei64) {
        src = (int)((const long long*)ei)[e];
        dst = (int)((const long long*)ei)[E + e];
    } else {
        src = ((const int*)ei)[e];
        dst = ((const int*)ei)[E + e];
    }
    int slot = atomicAdd(&g_cur[dst], 1);
    g_csr[slot] = src;
}

// ---------------------------------------------------------------------------
// tf32 HMMA GEMM: out[128-row tile][128] = X @ W, K=128.
// ---------------------------------------------------------------------------
__device__ __forceinline__ float to_tf32(float f) {
    uint32_t o;
    asm("cvt.rna.tf32.f32 %0, %1;" : "=r"(o) : "f"(f));
    return __uint_as_float(o);
}

__global__ void __launch_bounds__(256, 1)
gemm_mma(const float* __restrict__ X, const float* __restrict__ W,
         float* __restrict__ out) {
    extern __shared__ float sm[];
    float* Xs = sm;              // 128 x TS
    float* Ws = sm + 128 * TS;   // 128 x TS
    int tid = threadIdx.x;
    int r0 = blockIdx.x * 128;

#pragma unroll
    for (int j = 0; j < 16; j++) {
        int f = tid + j * 256;
        int row = f >> 5, c4 = f & 31;
        int gr = r0 + row;
        float4 v = make_float4(0.f, 0.f, 0.f, 0.f);
        if (gr < NN) v = ((const float4*)X)[gr * 32 + c4];
        v.x = to_tf32(v.x); v.y = to_tf32(v.y);
        v.z = to_tf32(v.z); v.w = to_tf32(v.w);
        *(float4*)(Xs + row * TS + c4 * 4) = v;
        float4 w = ((const float4*)W)[row * 32 + c4];
        w.x = to_tf32(w.x); w.y = to_tf32(w.y);
        w.z = to_tf32(w.z); w.w = to_tf32(w.w);
        *(float4*)(Ws + row * TS + c4 * 4) = w;
    }
    __syncthreads();

    int lane = tid & 31, wid = tid >> 5;
    int mw = (wid >> 1) * 32;
    int nw = (wid & 1) * 64;
    int gq = lane >> 2;
    int tq = lane & 3;

    float acc[2][8][4];
#pragma unroll
    for (int m = 0; m < 2; m++)
#pragma unroll
        for (int n = 0; n < 8; n++)
#pragma unroll
            for (int q = 0; q < 4; q++) acc[m][n][q] = 0.f;

#pragma unroll
    for (int kt = 0; kt < 16; kt++) {
        int k0 = kt * 8;
        uint32_t b0[8], b1[8];
        const float* wrow0 = Ws + (k0 + tq) * TS + nw + gq;
        const float* wrow1 = wrow0 + 4 * TS;
#pragma unroll
        for (int n = 0; n < 8; n++) {
            b0[n] = __float_as_uint(wrow0[n * 8]);
            b1[n] = __float_as_uint(wrow1[n * 8]);
        }
        uint32_t a[2][4];
#pragma unroll
        for (int m = 0; m < 2; m++) {
            const float* xr = Xs + (mw + m * 16 + gq) * TS + k0 + tq;
            a[m][0] = __float_as_uint(xr[0]);
            a[m][1] = __float_as_uint(xr[8 * TS]);
            a[m][2] = __float_as_uint(xr[4]);
            a[m][3] = __float_as_uint(xr[8 * TS + 4]);
        }
#pragma unroll
        for (int m = 0; m < 2; m++)
#pragma unroll
            for (int n = 0; n < 8; n++)
                asm volatile(
                    "mma.sync.aligned.m16n8k8.row.col.f32.tf32.tf32.f32 "
                    "{%0,%1,%2,%3}, {%4,%5,%6,%7}, {%8,%9}, {%0,%1,%2,%3};"
                    : "+f"(acc[m][n][0]), "+f"(acc[m][n][1]),
                      "+f"(acc[m][n][2]), "+f"(acc[m][n][3])
                    : "r"(a[m][0]), "r"(a[m][1]), "r"(a[m][2]), "r"(a[m][3]),
                      "r"(b0[n]), "r"(b1[n]));
    }

#pragma unroll
    for (int m = 0; m < 2; m++) {
        int r = r0 + mw + m * 16 + gq;
#pragma unroll
        for (int n = 0; n < 8; n++) {
            int c = nw + n * 8 + 2 * tq;
            if (r < NN)
                *(float2*)(out + r * HH + c) = make_float2(acc[m][n][0], acc[m][n][1]);
            if (r + 8 < NN)
                *(float2*)(out + (r + 8) * HH + c) = make_float2(acc[m][n][2], acc[m][n][3]);
        }
    }
}

// ---------------- CSR aggregation core (self-loop + bias + relu) ----------------
__device__ __forceinline__ float4 agg_row(const float* __restrict__ h,
                                          const float* __restrict__ bias,
                                          int w, int lane) {
    float dd = g_dis[w];
    float sc = dd * dd;
    float4 acc = __ldg((const float4*)h + w * 32 + lane);
    acc.x *= sc; acc.y *= sc; acc.z *= sc; acc.w *= sc;
    int beg = g_off[w], end = g_off[w + 1];
    int s0 = (beg < end) ? g_csr[beg] : 0;
    int s1 = (beg + 1 < end) ? g_csr[beg + 1] : 0;
    for (int e = beg; e < end; e++) {
        int s = s0;
        s0 = s1;
        s1 = (e + 2 < end) ? g_csr[e + 2] : 0;
        float nr = g_dis[s] * dd;
        float4 v = __ldg((const float4*)h + s * 32 + lane);
        acc.x = fmaf(v.x, nr, acc.x);
        acc.y = fmaf(v.y, nr, acc.y);
        acc.z = fmaf(v.z, nr, acc.z);
        acc.w = fmaf(v.w, nr, acc.w);
    }
    int c = lane * 4;
    acc.x = fmaxf(acc.x + __ldg(bias + c + 0), 0.f);
    acc.y = fmaxf(acc.y + __ldg(bias + c + 1), 0.f);
    acc.z = fmaxf(acc.z + __ldg(bias + c + 2), 0.f);
    acc.w = fmaxf(acc.w + __ldg(bias + c + 3), 0.f);
    return acc;
}

__global__ void agg_kernel(const float* __restrict__ h,
                           const float* __restrict__ bias,
                           float* __restrict__ out) {
    int w = (blockIdx.x * blockDim.x + threadIdx.x) >> 5;
    int lane = threadIdx.x & 31;
    if (w >= NN) return;
    float4 acc = agg_row(h, bias, w, lane);
    ((float4*)out)[w * 32 + lane] = acc;
}

// layer-2 agg fused with mean-pool accumulation: never materializes h2
__global__ void agg_pool_kernel(const float* __restrict__ h,
                                const float* __restrict__ bias,
                                const void* __restrict__ bat) {
    int w = (blockIdx.x * blockDim.x + threadIdx.x) >> 5;
    int lane = threadIdx.x & 31;
    if (w >= NN) return;
    float4 acc = agg_row(h, bias, w, lane);
    int b = g_b64 ? (int)((const long long*)bat)[w] : ((const int*)bat)[w];
    float* p = g_pool + b * HH + lane * 4;
    asm volatile("red.global.add.v4.f32 [%0], {%1,%2,%3,%4};"
                 :: "l"(p), "f"(acc.x), "f"(acc.y), "f"(acc.z), "f"(acc.w)
                 : "memory");
    if (lane == 0) atomicAdd(&g_cnt[b], 1.0f);
}

__global__ void final_kernel(const float* __restrict__ Wl,
                             const float* __restrict__ bl,
                             float* __restrict__ out) {
    int g = blockIdx.x;
    int lane = threadIdx.x;
    float c = fmaxf(g_cnt[g], 1.0f);
    float inv = 1.0f / c;
    float4 p = ((const float4*)g_pool)[g * 32 + lane];
    p.x *= inv; p.y *= inv; p.z *= inv; p.w *= inv;
    int r = lane * 4;
#pragma unroll
    for (int j = 0; j < CC; j++) {
        float s = p.x * __ldg(Wl + (r + 0) * CC + j)
                + p.y * __ldg(Wl + (r + 1) * CC + j)
                + p.z * __ldg(Wl + (r + 2) * CC + j)
                + p.w * __ldg(Wl + (r + 3) * CC + j);
#pragma unroll
        for (int off = 16; off; off >>= 1)
            s += __shfl_xor_sync(0xffffffffu, s, off);
        if (lane == 0) out[g * CC + j] = s + __ldg(bl + j);
    }
}

extern "C" void kernel_launch(void* const* d_in, const int* in_sizes, int n_in,
                              void* d_out, int out_size) {
    const float* x  = (const float*)d_in[0];
    const void*  ei = d_in[1];
    const void*  bat = d_in[2];
    const float* W1 = (const float*)d_in[3];
    const float* b1 = (const float*)d_in[4];
    const float* W2 = (const float*)d_in[5];
    const float* b2 = (const float*)d_in[6];
    const float* Wl = (const float*)d_in[7];
    const float* bl = (const float*)d_in[8];
    float* out = (float*)d_out;
    int E = in_sizes[1] / 2;

    const int SMEM_GEMM = 2 * 128 * TS * 4;   // 135168 B
    static cudaStream_t s2;
    static cudaEvent_t ev_fork, ev_join;
    static int once = 0;
    if (!once) {
        cudaFuncSetAttribute(gemm_mma, cudaFuncAttributeMaxDynamicSharedMemorySize,
                             SMEM_GEMM);
        cudaStreamCreateWithFlags(&s2, cudaStreamNonBlocking);
        cudaEventCreateWithFlags(&ev_fork, cudaEventDisableTiming);
        cudaEventCreateWithFlags(&ev_join, cudaEventDisableTiming);
        once = 1;
    }

    float *A, *B;
    cudaGetSymbolAddress((void**)&A, g_A);
    cudaGetSymbolAddress((void**)&B, g_B);

    int eb = (E + 255) / 256;
    int nb32 = (NN * 32 + 255) / 256;
    int gb = (NN + 127) / 128;

    // fork: GEMM1 (inputs only) runs parallel to the CSR-build chain
    cudaEventRecord(ev_fork, 0);
    cudaStreamWaitEvent(s2, ev_fork, 0);
    gemm_mma<<<gb, 256, SMEM_GEMM, s2>>>(x, W1, A);
    cudaEventRecord(ev_join, s2);

    init_detect_kernel<<<256, 256>>>((const unsigned*)ei, (const unsigned*)bat);
    deg_kernel<<<eb, 256>>>(ei, E);
    blocksum_kernel<<<SCAN_B, 256>>>();
    scanpart_kernel<<<1, 256>>>();
    offsets_kernel<<<SCAN_B, 256>>>();
    fill_kernel<<<eb, 256>>>(ei, E);

    cudaStreamWaitEvent(0, ev_join, 0);       // join before agg1
    agg_kernel<<<nb32, 256>>>(A, b1, B);
    gemm_mma<<<gb, 256, SMEM_GEMM>>>(B, W2, A);
    agg_pool_kernel<<<nb32, 256>>>(A, b2, bat);
    final_kernel<<<GG, 32>>>(Wl, bl, out);
}

// round 7
// speedup vs baseline: 2.4567x; 1.0496x over previous
#include <cuda_runtime.h>
#include <cstdint>

#define NN 50000
#define HH 128
#define GG 512
#define CC 10
#define EMAX 800000
#define TS 132        // padded SMEM row stride (floats)
#define SCAN_B 196    // ceil(NN/256)

// ---------------- scratch (no allocs allowed) ----------------
__device__ __align__(16) float g_dis[NN];
__device__ __align__(16) uint32_t g_Hbf[NN * 64];   // h as bf16x2 (gather target)
__device__ __align__(16) float g_B[NN * HH];        // fp32 intermediate
__device__ __align__(16) float g_pool[GG * HH];
__device__ float g_cnt[GG];
__device__ int   g_deg[NN];
__device__ int   g_off[NN + 1];
__device__ int   g_cur[NN];
__device__ int   g_csr[EMAX];
__device__ int   g_bsum[SCAN_B];
__device__ int g_ei64;
__device__ int g_b64;

__device__ __forceinline__ float blo(uint32_t v) { return __uint_as_float(v << 16); }
__device__ __forceinline__ float bhi(uint32_t v) { return __uint_as_float(v & 0xffff0000u); }
__device__ __forceinline__ uint32_t pack_bf16(float lo, float hi) {
    uint32_t r;
    asm("cvt.rn.bf16x2.f32 %0, %1, %2;" : "=r"(r) : "f"(hi), "f"(lo));
    return r;
}

// ---------------- init + dtype detect (merged) ----------------
__global__ void init_detect_kernel(const unsigned* __restrict__ ei,
                                   const unsigned* __restrict__ bat) {
    int i = blockIdx.x * blockDim.x + threadIdx.x;
    if (i < NN) g_deg[i] = 0;
    if (i < GG * HH) g_pool[i] = 0.0f;
    if (i < GG) g_cnt[i] = 0.0f;
    if (blockIdx.x == 0 && threadIdx.x < 32) {
        unsigned oe = 0, ob = 0;
        int lane = threadIdx.x;
        for (int j = lane; j < 1024; j += 32) {
            oe |= ei[2 * j + 1];
            ob |= bat[2 * j + 1];
        }
#pragma unroll
        for (int off = 16; off; off >>= 1) {
            oe |= __shfl_xor_sync(0xffffffffu, oe, off);
            ob |= __shfl_xor_sync(0xffffffffu, ob, off);
        }
        if (lane == 0) { g_ei64 = (oe == 0u); g_b64 = (ob == 0u); }
    }
}

__global__ void deg_kernel(const void* __restrict__ ei, int E) {
    int e = blockIdx.x * blockDim.x + threadIdx.x;
    if (e >= E) return;
    int dst = g_ei64 ? (int)((const long long*)ei)[E + e] : ((const int*)ei)[E + e];
    atomicAdd(&g_deg[dst], 1);
}

// ---------------- 3-phase chip-wide exclusive scan of g_deg ----------------
__global__ void blocksum_kernel() {
    int i = blockIdx.x * 256 + threadIdx.x;
    int d = (i < NN) ? g_deg[i] : 0;
    __shared__ int ws[8];
    int lane = threadIdx.x & 31, wid = threadIdx.x >> 5;
    int s = d;
#pragma unroll
    for (int off = 16; off; off >>= 1) s += __shfl_xor_sync(0xffffffffu, s, off);
    if (lane == 0) ws[wid] = s;
    __syncthreads();
    if (threadIdx.x == 0) {
        int t = 0;
#pragma unroll
        for (int w = 0; w < 8; w++) t += ws[w];
        g_bsum[blockIdx.x] = t;
    }
}

__global__ void scanpart_kernel() {
    __shared__ int sh[256];
    int t = threadIdx.x;
    int v = (t < SCAN_B) ? g_bsum[t] : 0;
    sh[t] = v;
    __syncthreads();
    for (int off = 1; off < 256; off <<= 1) {
        int u = (t >= off) ? sh[t - off] : 0;
        __syncthreads();
        sh[t] += u;
        __syncthreads();
    }
    if (t < SCAN_B) g_bsum[t] = sh[t] - v;          // exclusive
}

__global__ void offsets_kernel() {
    __shared__ int ws[8];
    int i = blockIdx.x * 256 + threadIdx.x;
    int lane = threadIdx.x & 31, wid = threadIdx.x >> 5;
    int d = (i < NN) ? g_deg[i] : 0;
    int incl = d;
#pragma unroll
    for (int off = 1; off < 32; off <<= 1) {
        int u = __shfl_up_sync(0xffffffffu, incl, off);
        if (lane >= off) incl += u;
    }
    if (lane == 31) ws[wid] = incl;
    __syncthreads();
    int wpre = 0;
#pragma unroll
    for (int w = 0; w < 8; w++) wpre += (w < wid) ? ws[w] : 0;
    int base = g_bsum[blockIdx.x] + wpre;
    int off0 = base + incl - d;
    if (i < NN) {
        g_off[i] = off0;
        g_cur[i] = off0;
        g_dis[i] = rsqrtf((float)d + 1.0f);
        if (i == NN - 1) g_off[NN] = off0 + d;
    }
}

__global__ void fill_kernel(const void* __restrict__ ei, int E) {
    int e = blockIdx.x * blockDim.x + threadIdx.x;
    if (e >= E) return;
    int src, dst;
    if (g_ei64) {
        src = (int)((const long long*)ei)[e];
        dst = (int)((const long long*)ei)[E + e];
    } else {
        src = ((const int*)ei)[e];
        dst = ((const int*)ei)[E + e];
    }
    int slot = atomicAdd(&g_cur[dst], 1);
    g_csr[slot] = src;
}

// ---------------------------------------------------------------------------
// tf32 HMMA GEMM: out_bf16[128-row tile][128] = X @ W, K=128.
// Epilogue packs adjacent column-pair accumulators to bf16x2.
// ---------------------------------------------------------------------------
__device__ __forceinline__ float to_tf32(float f) {
    uint32_t o;
    asm("cvt.rna.tf32.f32 %0, %1;" : "=r"(o) : "f"(f));
    return __uint_as_float(o);
}

__global__ void __launch_bounds__(256, 1)
gemm_mma(const float* __restrict__ X, const float* __restrict__ W,
         uint32_t* __restrict__ outb) {
    extern __shared__ float sm[];
    float* Xs = sm;              // 128 x TS
    float* Ws = sm + 128 * TS;   // 128 x TS
    int tid = threadIdx.x;
    int r0 = blockIdx.x * 128;

#pragma unroll
    for (int j = 0; j < 16; j++) {
        int f = tid + j * 256;
        int row = f >> 5, c4 = f & 31;
        int gr = r0 + row;
        float4 v = make_float4(0.f, 0.f, 0.f, 0.f);
        if (gr < NN) v = ((const float4*)X)[gr * 32 + c4];
        v.x = to_tf32(v.x); v.y = to_tf32(v.y);
        v.z = to_tf32(v.z); v.w = to_tf32(v.w);
        *(float4*)(Xs + row * TS + c4 * 4) = v;
        float4 w = ((const float4*)W)[row * 32 + c4];
        w.x = to_tf32(w.x); w.y = to_tf32(w.y);
        w.z = to_tf32(w.z); w.w = to_tf32(w.w);
        *(float4*)(Ws + row * TS + c4 * 4) = w;
    }
    __syncthreads();

    int lane = tid & 31, wid = tid >> 5;
    int mw = (wid >> 1) * 32;
    int nw = (wid & 1) * 64;
    int gq = lane >> 2;
    int tq = lane & 3;

    float acc[2][8][4];
#pragma unroll
    for (int m = 0; m < 2; m++)
#pragma unroll
        for (int n = 0; n < 8; n++)
#pragma unroll
            for (int q = 0; q < 4; q++) acc[m][n][q] = 0.f;

#pragma unroll
    for (int kt = 0; kt < 16; kt++) {
        int k0 = kt * 8;
        uint32_t b0[8], b1[8];
        const float* wrow0 = Ws + (k0 + tq) * TS + nw + gq;
        const float* wrow1 = wrow0 + 4 * TS;
#pragma unroll
        for (int n = 0; n < 8; n++) {
            b0[n] = __float_as_uint(wrow0[n * 8]);
            b1[n] = __float_as_uint(wrow1[n * 8]);
        }
        uint32_t a[2][4];
#pragma unroll
        for (int m = 0; m < 2; m++) {
            const float* xr = Xs + (mw + m * 16 + gq) * TS + k0 + tq;
            a[m][0] = __float_as_uint(xr[0]);
            a[m][1] = __float_as_uint(xr[8 * TS]);
            a[m][2] = __float_as_uint(xr[4]);
            a[m][3] = __float_as_uint(xr[8 * TS + 4]);
        }
#pragma unroll
        for (int m = 0; m < 2; m++)
#pragma unroll
            for (int n = 0; n < 8; n++)
                asm volatile(
                    "mma.sync.aligned.m16n8k8.row.col.f32.tf32.tf32.f32 "
                    "{%0,%1,%2,%3}, {%4,%5,%6,%7}, {%8,%9}, {%0,%1,%2,%3};"
                    : "+f"(acc[m][n][0]), "+f"(acc[m][n][1]),
                      "+f"(acc[m][n][2]), "+f"(acc[m][n][3])
                    : "r"(a[m][0]), "r"(a[m][1]), "r"(a[m][2]), "r"(a[m][3]),
                      "r"(b0[n]), "r"(b1[n]));
    }

#pragma unroll
    for (int m = 0; m < 2; m++) {
        int r = r0 + mw + m * 16 + gq;
#pragma unroll
        for (int n = 0; n < 8; n++) {
            int cp = (nw >> 1) + n * 4 + tq;     // bf16x2 column index
            if (r < NN)
                outb[r * 64 + cp] = pack_bf16(acc[m][n][0], acc[m][n][1]);
            if (r + 8 < NN)
                outb[(r + 8) * 64 + cp] = pack_bf16(acc[m][n][2], acc[m][n][3]);
        }
    }
}

// ---------------- CSR aggregation core (bf16 gather, fp32 accumulate) ----------
__device__ __forceinline__ float4 agg_row(const uint32_t* __restrict__ hb,
                                          const float* __restrict__ bias,
                                          int w, int lane) {
    float dd = g_dis[w];
    float sc = dd * dd;
    uint2 sv = __ldg((const uint2*)hb + w * 32 + lane);
    float4 acc;
    acc.x = blo(sv.x) * sc;
    acc.y = bhi(sv.x) * sc;
    acc.z = blo(sv.y) * sc;
    acc.w = bhi(sv.y) * sc;
    int beg = g_off[w], end = g_off[w + 1];
    int s0 = (beg < end) ? g_csr[beg] : 0;
    int s1 = (beg + 1 < end) ? g_csr[beg + 1] : 0;
    for (int e = beg; e < end; e++) {
        int s = s0;
        s0 = s1;
        s1 = (e + 2 < end) ? g_csr[e + 2] : 0;
        float nr = g_dis[s] * dd;
        uint2 pv = __ldg((const uint2*)hb + s * 32 + lane);
        acc.x = fmaf(blo(pv.x), nr, acc.x);
        acc.y = fmaf(bhi(pv.x), nr, acc.y);
        acc.z = fmaf(blo(pv.y), nr, acc.z);
        acc.w = fmaf(bhi(pv.y), nr, acc.w);
    }
    int c = lane * 4;
    acc.x = fmaxf(acc.x + __ldg(bias + c + 0), 0.f);
    acc.y = fmaxf(acc.y + __ldg(bias + c + 1), 0.f);
    acc.z = fmaxf(acc.z + __ldg(bias + c + 2), 0.f);
    acc.w = fmaxf(acc.w + __ldg(bias + c + 3), 0.f);
    return acc;
}

__global__ void agg_kernel(const uint32_t* __restrict__ hb,
                           const float* __restrict__ bias,
                           float* __restrict__ out) {
    int w = (blockIdx.x * blockDim.x + threadIdx.x) >> 5;
    int lane = threadIdx.x & 31;
    if (w >= NN) return;
    float4 acc = agg_row(hb, bias, w, lane);
    ((float4*)out)[w * 32 + lane] = acc;
}

// layer-2 agg fused with mean-pool accumulation: never materializes h2
__global__ void agg_pool_kernel(const uint32_t* __restrict__ hb,
                                const float* __restrict__ bias,
                                const void* __restrict__ bat) {
    int w = (blockIdx.x * blockDim.x + threadIdx.x) >> 5;
    int lane = threadIdx.x & 31;
    if (w >= NN) return;
    float4 acc = agg_row(hb, bias, w, lane);
    int b = g_b64 ? (int)((const long long*)bat)[w] : ((const int*)bat)[w];
    float* p = g_pool + b * HH + lane * 4;
    asm volatile("red.global.add.v4.f32 [%0], {%1,%2,%3,%4};"
                 :: "l"(p), "f"(acc.x), "f"(acc.y), "f"(acc.z), "f"(acc.w)
                 : "memory");
    if (lane == 0) atomicAdd(&g_cnt[b], 1.0f);
}

__global__ void final_kernel(const float* __restrict__ Wl,
                             const float* __restrict__ bl,
                             float* __restrict__ out) {
    int g = blockIdx.x;
    int lane = threadIdx.x;
    float c = fmaxf(g_cnt[g], 1.0f);
    float inv = 1.0f / c;
    float4 p = ((const float4*)g_pool)[g * 32 + lane];
    p.x *= inv; p.y *= inv; p.z *= inv; p.w *= inv;
    int r = lane * 4;
#pragma unroll
    for (int j = 0; j < CC; j++) {
        float s = p.x * __ldg(Wl + (r + 0) * CC + j)
                + p.y * __ldg(Wl + (r + 1) * CC + j)
                + p.z * __ldg(Wl + (r + 2) * CC + j)
                + p.w * __ldg(Wl + (r + 3) * CC + j);
#pragma unroll
        for (int off = 16; off; off >>= 1)
            s += __shfl_xor_sync(0xffffffffu, s, off);
        if (lane == 0) out[g * CC + j] = s + __ldg(bl + j);
    }
}

extern "C" void kernel_launch(void* const* d_in, const int* in_sizes, int n_in,
                              void* d_out, int out_size) {
    const float* x  = (const float*)d_in[0];
    const void*  ei = d_in[1];
    const void*  bat = d_in[2];
    const float* W1 = (const float*)d_in[3];
    const float* b1 = (const float*)d_in[4];
    const float* W2 = (const float*)d_in[5];
    const float* b2 = (const float*)d_in[6];
    const float* Wl = (const float*)d_in[7];
    const float* bl = (const float*)d_in[8];
    float* out = (float*)d_out;
    int E = in_sizes[1] / 2;

    const int SMEM_GEMM = 2 * 128 * TS * 4;   // 135168 B
    static cudaStream_t s2;
    static cudaEvent_t ev_fork, ev_join;
    static int once = 0;
    if (!once) {
        cudaFuncSetAttribute(gemm_mma, cudaFuncAttributeMaxDynamicSharedMemorySize,
                             SMEM_GEMM);
        cudaStreamCreateWithFlags(&s2, cudaStreamNonBlocking);
        cudaEventCreateWithFlags(&ev_fork, cudaEventDisableTiming);
        cudaEventCreateWithFlags(&ev_join, cudaEventDisableTiming);
        once = 1;
    }

    uint32_t* Hb;
    float* B;
    cudaGetSymbolAddress((void**)&Hb, g_Hbf);
    cudaGetSymbolAddress((void**)&B, g_B);

    int eb = (E + 255) / 256;
    int nb32 = (NN * 32 + 255) / 256;
    int gb = (NN + 127) / 128;

    // fork: GEMM1 (inputs only) runs parallel to the CSR-build chain
    cudaEventRecord(ev_fork, 0);
    cudaStreamWaitEvent(s2, ev_fork, 0);
    gemm_mma<<<gb, 256, SMEM_GEMM, s2>>>(x, W1, Hb);
    cudaEventRecord(ev_join, s2);

    init_detect_kernel<<<256, 256>>>((const unsigned*)ei, (const unsigned*)bat);
    deg_kernel<<<eb, 256>>>(ei, E);
    blocksum_kernel<<<SCAN_B, 256>>>();
    scanpart_kernel<<<1, 256>>>();
    offsets_kernel<<<SCAN_B, 256>>>();
    fill_kernel<<<eb, 256>>>(ei, E);

    cudaStreamWaitEvent(0, ev_join, 0);       // join before agg1
    agg_kernel<<<nb32, 256>>>(Hb, b1, B);
    gemm_mma<<<gb, 256, SMEM_GEMM>>>(B, W2, Hb);
    agg_pool_kernel<<<nb32, 256>>>(Hb, b2, bat);
    final_kernel<<<GG, 32>>>(Wl, bl, out);
}